// round 17
// baseline (speedup 1.0000x reference)
#include <cuda_runtime.h>
#include <cstdint>

#define H        768
#define CKF      16                     // k per chunk
#define NCH      48                     // chunks per tile
#define SLOTS    4                      // ring slots
#define TROWS    512                    // rows per tile
#define G        4                      // rows per lane (consumer)
#define CONS     8                      // consumer warps (4 pairs x 2)
#define PROD     4                      // producer warps
#define THREADS  ((CONS + PROD) * 32)   // 384
#define CHUNK_FLOATS (TROWS * CKF)      // 8192 floats = 32 KB
#define CHUNK_BYTES  (CHUNK_FLOATS * 4)
#define W4_FLOATS (H * 16)              // [H][4] float4
#define W1_FLOATS (H)
#define WB_FLOATS 32
#define WX_FLOATS (W4_FLOATS + W1_FLOATS + WB_FLOATS)
#define RING_FLOATS (SLOTS * CHUNK_FLOATS)          // 128 KB
#define SCR_FLOATS  (4 * 128 * 18)                  // pair combine scratch, 36 KB
#define SMEM_BYTES ((WX_FLOATS + RING_FLOATS + SCR_FLOATS) * 4)  // 220288 B

// 17 fused channels: a0,a1 | b0..b3 | c1_0,c1_1 | c2_0..2 | c3_0..3 | c4_0,c4_1

__device__ __forceinline__ void ffma2(float2& d, const float2 a, const float2 b)
{
    asm("fma.rn.f32x2 %0, %1, %2, %0;"
        : "+l"(reinterpret_cast<unsigned long long&>(d))
        : "l"(reinterpret_cast<const unsigned long long&>(a)),
          "l"(reinterpret_cast<const unsigned long long&>(b)));
}
__device__ __forceinline__ void cp16(uint32_t saddr, const void* gptr)
{
    asm volatile("cp.async.cg.shared.global [%0], [%1], 16;"
                 :: "r"(saddr), "l"(gptr) : "memory");
}
__device__ __forceinline__ void cp_commit()
{
    asm volatile("cp.async.commit_group;" ::: "memory");
}
template <int N>
__device__ __forceinline__ void cp_wait()
{
    asm volatile("cp.async.wait_group %0;" :: "n"(N) : "memory");
}
__device__ __forceinline__ void bar_sync_all(int id)
{
    asm volatile("bar.sync %0, %1;" :: "r"(id), "r"(THREADS) : "memory");
}
__device__ __forceinline__ void bar_arrive_all(int id)
{
    asm volatile("bar.arrive %0, %1;" :: "r"(id), "r"(THREADS) : "memory");
}
__device__ __forceinline__ void pair_bar(int id)
{
    asm volatile("bar.sync %0, 64;" :: "r"(id) : "memory");
}

// ---------------------------------------------------------------------------
// Warp-specialized kernel, 1 CTA/SM:
//   warps 0..7  : consumers. Pair p (=wid>>1) owns rows [p*128,(p+1)*128) of
//                 the 512-row tile; within a pair, warp pw (=wid&1) computes
//                 k-half pw of each 16-k chunk (4 rows/lane, partials
//                 combined via smem scratch at tile end).
//   warps 8..11 : producers. Pure cp.async issuers; producer pid loads rows
//                 [pid*128,(pid+1)*128) of each chunk into a 4-slot CTA ring.
// Ring slot layout: [4 jg][512 rows][16 B] (jg = k-quad) -> coalesced 128 B
// cp stores and conflict-free LDS.128 reads.
// full[slot]=bar 1+slot, empty[slot]=bar 5+slot (count 384: sync one side,
// arrive the other). Pair combine barriers: 9+pair (count 64).
// NCH % SLOTS == 0, so slot == c & 3 in every tile.
// ---------------------------------------------------------------------------
extern __shared__ float smem[];

__global__ void __launch_bounds__(THREADS)
main_kernel(const float* __restrict__ x, float* __restrict__ out,
            const float* __restrict__ Wa,  const float* __restrict__ ba,
            const float* __restrict__ Wb,  const float* __restrict__ bb,
            const float* __restrict__ Wc1, const float* __restrict__ bc1,
            const float* __restrict__ Wc2, const float* __restrict__ bc2,
            const float* __restrict__ Wc3, const float* __restrict__ bc3,
            const float* __restrict__ Wc4, const float* __restrict__ bc4,
            int B, int ntiles)
{
    const int wid  = threadIdx.x >> 5;
    const int lane = threadIdx.x & 31;
    const int grid = gridDim.x;
    const int bid  = blockIdx.x;

    float4* sw4   = reinterpret_cast<float4*>(smem);   // [H][4]
    float*  sw1   = smem + W4_FLOATS;                  // [H]
    float*  sbias = sw1 + W1_FLOATS;                   // [17]
    float*  ring  = smem + WX_FLOATS;                  // [SLOTS][CHUNK_FLOATS]
    float*  scr   = ring + RING_FLOATS;                // [4][128][18]

    // ---- pack weights + bias into smem once per CTA ----
    auto getw = [&](int ch, int k) -> float {
        if (ch < 2)  return Wa [ ch        * H + k];
        if (ch < 6)  return Wb [(ch - 2)  * H + k];
        if (ch < 8)  return Wc1[(ch - 6)  * H + k];
        if (ch < 11) return Wc2[(ch - 8)  * H + k];
        if (ch < 15) return Wc3[(ch - 11) * H + k];
        return Wc4[(ch - 15) * H + k];
    };
    for (int i = threadIdx.x; i < H * 4; i += THREADS) {
        const int k = i >> 2, p = i & 3;
        sw4[i] = make_float4(getw(4 * p, k),     getw(4 * p + 1, k),
                             getw(4 * p + 2, k), getw(4 * p + 3, k));
    }
    for (int i = threadIdx.x; i < H; i += THREADS)
        sw1[i] = getw(16, i);
    if (threadIdx.x < 17) {
        const int ch = threadIdx.x; float b;
        if      (ch < 2)  b = ba [ch];
        else if (ch < 6)  b = bb [ch - 2];
        else if (ch < 8)  b = bc1[ch - 6];
        else if (ch < 11) b = bc2[ch - 8];
        else if (ch < 15) b = bc3[ch - 11];
        else              b = bc4[ch - 15];
        sbias[ch] = b;
    }
    __syncthreads();   // bar 0

    if (wid >= CONS) {
        // ================= PRODUCER =================
        const int pid   = wid - CONS;              // 0..3
        const int crow  = lane >> 2;               // 0..7
        const int cpart = lane & 3;                // 0..3 == jg
        const uint32_t rsb = (uint32_t)__cvta_generic_to_shared(ring);
        const int rlocal = pid * 128 + crow;       // row base within chunk

        auto issue = [&](int tile, int c, int slot) {
            const size_t row0 = (size_t)tile * TROWS;
            const float* gsrc = x + (row0 + rlocal) * H + c * CKF + cpart * 4;
            const uint32_t d0 = rsb + slot * CHUNK_BYTES + cpart * 8192
                                    + rlocal * 16;
            #pragma unroll
            for (int i = 0; i < 16; ++i) {         // 16 x 8 rows = 128 rows
                if ((int)row0 + rlocal + i * 8 < B)
                    cp16(d0 + i * 8 * 16, gsrc + (size_t)(i * 8) * H);
            }
        };

        int lt = bid, lc = 0;                      // load cursor (tile, chunk)
        const int ntloc = (bid < ntiles) ? (ntiles - 1 - bid) / grid + 1 : 0;
        const long total = (long)ntloc * NCH;

        #pragma unroll
        for (int j = 0; j < SLOTS; ++j) {          // prime 4 chunks
            if (lt < ntiles) {
                issue(lt, lc, lc & 3);
                if (++lc == NCH) { lc = 0; lt += grid; }
            }
            cp_commit();
        }
        for (long seq = 0; seq < total; ++seq) {
            cp_wait<SLOTS - 1>();                  // my part of chunk seq done
            bar_arrive_all(1 + (int)(seq & 3));    // full[slot]
            if (lt < ntiles) {
                bar_sync_all(5 + (lc & 3));        // empty[slot of chunk seq+4]
                issue(lt, lc, lc & 3);
                if (++lc == NCH) { lc = 0; lt += grid; }
            }
            cp_commit();                           // real or empty group
        }
    } else {
        // ================= CONSUMER =================
        const int pair = wid >> 1;                 // 0..3
        const int pw   = wid & 1;                  // k-half

        for (int tile = bid; tile < ntiles; tile += grid) {
            const int row0 = tile * TROWS;

            float2 acc[G][8];
            float  a16[G];
            #pragma unroll
            for (int g = 0; g < G; ++g) {
                #pragma unroll
                for (int p = 0; p < 8; ++p) acc[g][p] = make_float2(0.f, 0.f);
                a16[g] = 0.f;
            }

            for (int c = 0; c < NCH; ++c) {
                const int slot = c & 3;
                bar_sync_all(1 + slot);            // wait full

                const float* xb = ring + slot * CHUNK_FLOATS + (pw * 2) * 2048;
                #pragma unroll
                for (int jj = 0; jj < 2; ++jj) {
                    float4 xv[G];
                    #pragma unroll
                    for (int g = 0; g < G; ++g) {
                        const int r = pair * 128 + lane + 32 * g;
                        xv[g] = *reinterpret_cast<const float4*>(
                            xb + jj * 2048 + r * 4);
                    }
                    const int kb = c * CKF + pw * 8 + jj * 4;
                    #pragma unroll
                    for (int j = 0; j < 4; ++j) {
                        const int k = kb + j;
                        const float4* wk = sw4 + k * 4;  // broadcast LDS
                        const float4 w0 = wk[0];
                        const float4 w1 = wk[1];
                        const float4 w2 = wk[2];
                        const float4 w3 = wk[3];
                        const float  wl = sw1[k];
                        #pragma unroll
                        for (int g = 0; g < G; ++g) {
                            const float xk = (j == 0) ? xv[g].x
                                           : (j == 1) ? xv[g].y
                                           : (j == 2) ? xv[g].z : xv[g].w;
                            const float2 xd = make_float2(xk, xk);
                            ffma2(acc[g][0], xd, make_float2(w0.x, w0.y));
                            ffma2(acc[g][1], xd, make_float2(w0.z, w0.w));
                            ffma2(acc[g][2], xd, make_float2(w1.x, w1.y));
                            ffma2(acc[g][3], xd, make_float2(w1.z, w1.w));
                            ffma2(acc[g][4], xd, make_float2(w2.x, w2.y));
                            ffma2(acc[g][5], xd, make_float2(w2.z, w2.w));
                            ffma2(acc[g][6], xd, make_float2(w3.x, w3.y));
                            ffma2(acc[g][7], xd, make_float2(w3.z, w3.w));
                            a16[g] = fmaf(xk, wl, a16[g]);
                        }
                    }
                }
                bar_arrive_all(5 + slot);          // release slot
            }

            // --- combine k-halves via scratch, then epilogue (warp pw==0) ---
            float* sc = scr + pair * (128 * 18);
            if (pw == 1) {
                #pragma unroll
                for (int g = 0; g < G; ++g) {
                    const int rl = lane + 32 * g;
                    float* dst = sc + rl * 18;
                    #pragma unroll
                    for (int p = 0; p < 8; ++p)
                        *reinterpret_cast<float2*>(dst + 2 * p) = acc[g][p];
                    dst[16] = a16[g];
                }
            }
            pair_bar(9 + pair);

            if (pw == 0) {
                #pragma unroll
                for (int g = 0; g < G; ++g) {
                    const int rl = lane + 32 * g;
                    const int r  = row0 + pair * 128 + rl;
                    if (r >= B) continue;
                    const float* src = sc + rl * 18;

                    float v[17];
                    #pragma unroll
                    for (int p = 0; p < 8; ++p) {
                        const float2 o =
                            *reinterpret_cast<const float2*>(src + 2 * p);
                        v[2 * p]     = acc[g][p].x + o.x + sbias[2 * p];
                        v[2 * p + 1] = acc[g][p].y + o.y + sbias[2 * p + 1];
                    }
                    v[16] = a16[g] + src[16] + sbias[16];

                    const bool active = v[1] > v[0];          // argmax != 0

                    ((float2*)out)[r] = make_float2(v[0], v[1]);   // out_a

                    int pb = 0; float best = v[2];
                    if (v[3] > best) { pb = 1; best = v[3]; }
                    if (v[4] > best) { pb = 2; best = v[4]; }
                    if (v[5] > best) { pb = 3; best = v[5]; }

                    float* ob = out + 2 * (size_t)B + 5 * (size_t)r;  // out_b
                    ob[0] = 0.0f;
                    #pragma unroll
                    for (int j = 0; j < 4; ++j)
                        ob[j + 1] = active ? v[2 + j] : 0.0f;

                    float* oc = out + 7 * (size_t)B + 11 * (size_t)r; // out_c
                    #pragma unroll
                    for (int j = 0; j < 11; ++j) {
                        const int hd = (j < 2) ? 0 : (j < 5) ? 1
                                     : (j < 9) ? 2 : 3;
                        oc[j] = (active && hd == pb) ? v[6 + j] : 0.0f;
                    }
                }
            }
            pair_bar(9 + pair);   // scratch reusable for next tile
        }
    }
}

// ---------------------------------------------------------------------------
extern "C" void kernel_launch(void* const* d_in, const int* in_sizes, int n_in,
                              void* d_out, int out_size)
{
    const float* x = (const float*)d_in[0];
    const int B = in_sizes[0] / H;
    const int ntiles = (B + TROWS - 1) / TROWS;    // 256 for B=131072
    const int grid   = 148;                         // 1 CTA/SM

    cudaFuncSetAttribute(main_kernel,
                         cudaFuncAttributeMaxDynamicSharedMemorySize, SMEM_BYTES);
    main_kernel<<<grid, THREADS, SMEM_BYTES>>>(
        x, (float*)d_out,
        (const float*)d_in[1],  (const float*)d_in[2],
        (const float*)d_in[3],  (const float*)d_in[4],
        (const float*)d_in[5],  (const float*)d_in[6],
        (const float*)d_in[7],  (const float*)d_in[8],
        (const float*)d_in[9],  (const float*)d_in[10],
        (const float*)d_in[11], (const float*)d_in[12],
        B, ntiles);
}